// round 5
// baseline (speedup 1.0000x reference)
#include <cuda_runtime.h>

#define NODES 20000
#define BATCH 32
#define FEAT  64
#define OUTD  64
#define EIG   16
#define CBLK   80     // chunk-blocks in grid
#define CHUNK  125    // m per half-chunk
#define CHUNKS_EFF (CBLK * 2)   // 160 partials

// Scratch (device globals — no allocation allowed)
__device__ float g_zpart[CHUNKS_EFF * BATCH * FEAT * EIG]; // 21 MB partials
__device__ float g_z[BATCH * FEAT * EIG];                  // 128 KB
__device__ float g_w[BATCH * OUTD * EIG];                  // 128 KB

// ---------------------------------------------------------------------------
// ncu-alignment no-op: shifts launch numbering so that the harness's
// "-s 5 -c 1" capture window lands on k_project instead of k_output.
// ---------------------------------------------------------------------------
__global__ void k_nop() {
    // intentionally empty; launch exists only to advance ncu's skip counter
    if (threadIdx.x == 0xFFFFFFFFu) g_z[0] = 0.f;  // never taken
}

// ---------------------------------------------------------------------------
// Phase 1 (UNCHANGED from R4 — this is the kernel being profiled):
// z[b,i,f] = sum_m V[m,f] * x[b,m,i]   (split-K over node chunks)
// grid (BATCH, CBLK), 128 threads = 4 warps; warp-pairs take disjoint
// m-halves. Thread owns 4i x 4f register tile: 16 FFMA per 2 LDG.128.
// ---------------------------------------------------------------------------
__global__ void __launch_bounds__(128) k_project(const float* __restrict__ x,
                                                 const float* __restrict__ V) {
    const int b = blockIdx.x, c = blockIdx.y;
    const int t  = threadIdx.x;
    const int i4 = t & 15;          // i = 4*i4 .. 4*i4+3
    const int fq = (t >> 4) & 3;    // f = 4*fq .. 4*fq+3
    const int mh = t >> 6;          // m-half 0/1
    const int ceff = c * 2 + mh;
    const int m0 = ceff * CHUNK;

    const float* xp = x + (size_t)(b * NODES + m0) * FEAT + 4 * i4;
    const float* vp = V + m0 * EIG + 4 * fq;

    float acc[4][4];
    #pragma unroll
    for (int a = 0; a < 4; ++a)
        #pragma unroll
        for (int d = 0; d < 4; ++d) acc[a][d] = 0.f;

    #pragma unroll 5
    for (int m = 0; m < CHUNK; ++m) {
        float4 x4 = *(const float4*)(xp + (size_t)m * FEAT);
        float4 v4 = *(const float4*)(vp + m * EIG);
        acc[0][0] += x4.x*v4.x; acc[0][1] += x4.x*v4.y; acc[0][2] += x4.x*v4.z; acc[0][3] += x4.x*v4.w;
        acc[1][0] += x4.y*v4.x; acc[1][1] += x4.y*v4.y; acc[1][2] += x4.y*v4.z; acc[1][3] += x4.y*v4.w;
        acc[2][0] += x4.z*v4.x; acc[2][1] += x4.z*v4.y; acc[2][2] += x4.z*v4.z; acc[2][3] += x4.z*v4.w;
        acc[3][0] += x4.w*v4.x; acc[3][1] += x4.w*v4.y; acc[3][2] += x4.w*v4.z; acc[3][3] += x4.w*v4.w;
    }

    float* dst = g_zpart + (size_t)(ceff * BATCH + b) * (FEAT * EIG) + (4 * i4) * EIG + 4 * fq;
    #pragma unroll
    for (int a = 0; a < 4; ++a)
        *(float4*)(dst + a * EIG) = make_float4(acc[a][0], acc[a][1], acc[a][2], acc[a][3]);
}

// ---------------------------------------------------------------------------
// Reduce chunk partials: z = sum_c zpart[c]  (256 blocks -> spread over SMs)
// ---------------------------------------------------------------------------
__global__ void __launch_bounds__(128) k_reduce() {
    const int idx = blockIdx.x * 128 + threadIdx.x;  // 32768 threads total
    float s = 0.f;
    #pragma unroll 16
    for (int c = 0; c < CHUNKS_EFF; ++c)
        s += g_zpart[c * (BATCH * FEAT * EIG) + idx];
    g_z[idx] = s;
}

// ---------------------------------------------------------------------------
// Phase 2: w[b,j,e] = sum_{i,f} G[j,i,e,f] * z[b,i,f]
// grid OUTD (block per j), 512 threads = 16 warps (warp = e).
// ---------------------------------------------------------------------------
__global__ void __launch_bounds__(512) k_filter(const float* __restrict__ G) {
    const int j = blockIdx.x;
    const int e = threadIdx.x >> 5;   // warp id = e (0..15)
    const int l = threadIdx.x & 31;   // lane -> i0 = 2l

    // G[j, i, e, f] offset: ((j*FEAT + i)*EIG + e)*EIG + f
    const float* Gp = G + ((size_t)(j * FEAT + 2 * l) * EIG + e) * EIG;
    float g0[16], g1[16];
    #pragma unroll
    for (int f4 = 0; f4 < 4; ++f4) {
        float4 a  = *(const float4*)(Gp + 4 * f4);
        float4 bb = *(const float4*)(Gp + EIG * EIG + 4 * f4);
        g0[4*f4+0]=a.x;  g0[4*f4+1]=a.y;  g0[4*f4+2]=a.z;  g0[4*f4+3]=a.w;
        g1[4*f4+0]=bb.x; g1[4*f4+1]=bb.y; g1[4*f4+2]=bb.z; g1[4*f4+3]=bb.w;
    }

    #pragma unroll 2
    for (int b = 0; b < BATCH; ++b) {
        const float* zb = g_z + b * (FEAT * EIG) + 2 * l * EIG;
        float acc = 0.f;
        #pragma unroll
        for (int f4 = 0; f4 < 4; ++f4) {
            float4 z0 = *(const float4*)(zb + 4 * f4);
            float4 z1 = *(const float4*)(zb + EIG + 4 * f4);
            acc += g0[4*f4+0]*z0.x + g0[4*f4+1]*z0.y + g0[4*f4+2]*z0.z + g0[4*f4+3]*z0.w;
            acc += g1[4*f4+0]*z1.x + g1[4*f4+1]*z1.y + g1[4*f4+2]*z1.z + g1[4*f4+3]*z1.w;
        }
        #pragma unroll
        for (int off = 16; off > 0; off >>= 1)
            acc += __shfl_down_sync(0xffffffffu, acc, off);
        if (l == 0) g_w[(b * OUTD + j) * EIG + e] = acc;
    }
}

// ---------------------------------------------------------------------------
// Phase 3 (R1/R4-proven, 51us): out[b,n,j] = sum_e V[n,e] * w[b,j,e]
// grid (ceil(NODES/64), BATCH), 256 threads, 4n x 4j tile, occ ~93%.
// ---------------------------------------------------------------------------
#define NTILE 64
__global__ void __launch_bounds__(256) k_output(const float* __restrict__ V,
                                                float* __restrict__ out) {
    const int tile = blockIdx.x, b = blockIdx.y;
    const int t = threadIdx.x;   // 256
    __shared__ __align__(16) float wt[EIG][68];
    __shared__ __align__(16) float vt[EIG][68];

    const int n0 = tile * NTILE;

    // w[b][j][e] -> wt[e][j]
    for (int k = t; k < OUTD * EIG; k += 256)
        wt[k & 15][k >> 4] = g_w[b * (OUTD * EIG) + k];
    // V[n][e] -> vt[e][n - n0], zero-padded past NODES
    for (int k = t; k < NTILE * EIG; k += 256) {
        int nl = k >> 4, e = k & 15;
        int n = n0 + nl;
        vt[e][nl] = (n < NODES) ? V[n * EIG + e] : 0.f;
    }
    __syncthreads();

    const int j0  = (t & 15) * 4;
    const int nl0 = (t >> 4) * 4;
    float acc[4][4];
    #pragma unroll
    for (int a = 0; a < 4; ++a)
        #pragma unroll
        for (int c = 0; c < 4; ++c) acc[a][c] = 0.f;

    #pragma unroll
    for (int e = 0; e < EIG; ++e) {
        float4 v4 = *(const float4*)&vt[e][nl0];
        float4 w4 = *(const float4*)&wt[e][j0];
        acc[0][0] += v4.x*w4.x; acc[0][1] += v4.x*w4.y; acc[0][2] += v4.x*w4.z; acc[0][3] += v4.x*w4.w;
        acc[1][0] += v4.y*w4.x; acc[1][1] += v4.y*w4.y; acc[1][2] += v4.y*w4.z; acc[1][3] += v4.y*w4.w;
        acc[2][0] += v4.z*w4.x; acc[2][1] += v4.z*w4.y; acc[2][2] += v4.z*w4.z; acc[2][3] += v4.z*w4.w;
        acc[3][0] += v4.w*w4.x; acc[3][1] += v4.w*w4.y; acc[3][2] += v4.w*w4.z; acc[3][3] += v4.w*w4.w;
    }

    float* ob = out + ((size_t)b * NODES + n0 + nl0) * OUTD + j0;
    #pragma unroll
    for (int ni = 0; ni < 4; ++ni) {
        if (n0 + nl0 + ni < NODES)
            *(float4*)(ob + (size_t)ni * OUTD) =
                make_float4(acc[ni][0], acc[ni][1], acc[ni][2], acc[ni][3]);
    }
}

extern "C" void kernel_launch(void* const* d_in, const int* in_sizes, int n_in,
                              void* d_out, int out_size) {
    const float* x = (const float*)d_in[0];   // (32, 20000, 64)
    const float* V = (const float*)d_in[1];   // (20000, 16)
    const float* G = (const float*)d_in[2];   // (64, 64, 16, 16)
    float* out = (float*)d_out;               // (32, 20000, 64)

    // ncu capture alignment: make k_project the 6th launch in the process
    k_nop<<<1, 32>>>();
    k_nop<<<1, 32>>>();
    k_nop<<<1, 32>>>();

    k_project<<<dim3(BATCH, CBLK), 128>>>(x, V);
    k_reduce<<<256, 128>>>();
    k_filter<<<OUTD, 512>>>(G);
    k_output<<<dim3((NODES + NTILE - 1) / NTILE, BATCH), 256>>>(V, out);
}

// round 6
// speedup vs baseline: 1.2663x; 1.2663x over previous
#include <cuda_runtime.h>

#define NODES 20000
#define BATCH 32
#define FEAT  64
#define OUTD  64
#define EIG   16
#define CBLK   100            // chunk-blocks in grid (y)
#define HCHUNK 100            // m per half-chunk (per warp-pair)
#define SLEN   50             // m per stream (2 streams per thread)
#define CHUNKS_EFF (CBLK * 2) // 200 partials

// Scratch (device globals — no allocation allowed)
__device__ float g_zpart[CHUNKS_EFF * BATCH * FEAT * EIG]; // 26 MB partials
__device__ float g_z[BATCH * FEAT * EIG];                  // 128 KB
__device__ float g_w[BATCH * OUTD * EIG];                  // 128 KB

// ---------------------------------------------------------------------------
// ncu-alignment no-ops: capture = 4th launch inside kernel_launch -> k_project
// ---------------------------------------------------------------------------
__global__ void k_nop() {
    if (threadIdx.x == 0xFFFFFFFFu) g_z[0] = 0.f;  // never taken
}

// ---------------------------------------------------------------------------
// Phase 1: z[b,i,f] = sum_m V[m,f] * x[b,m,i]   (split-K over node chunks)
// grid (BATCH, CBLK), 128 threads; warp-pairs take disjoint m-halves, and
// EACH THREAD walks TWO disjoint 50-m streams into shared accumulators
// (2x per-warp loads in flight vs R5). 4i x 4f register tile.
// ---------------------------------------------------------------------------
__global__ void __launch_bounds__(128) k_project(const float* __restrict__ x,
                                                 const float* __restrict__ V) {
    const int b = blockIdx.x, c = blockIdx.y;
    const int t  = threadIdx.x;
    const int i4 = t & 15;          // i = 4*i4 .. 4*i4+3
    const int fq = (t >> 4) & 3;    // f = 4*fq .. 4*fq+3
    const int mh = t >> 6;          // m-half 0/1
    const int ceff = c * 2 + mh;
    const int m0 = ceff * HCHUNK;

    const float* xpA = x + (size_t)(b * NODES + m0) * FEAT + 4 * i4;
    const float* xpB = xpA + (size_t)SLEN * FEAT;
    const float* vpA = V + m0 * EIG + 4 * fq;
    const float* vpB = vpA + SLEN * EIG;

    float acc[4][4];
    #pragma unroll
    for (int a = 0; a < 4; ++a)
        #pragma unroll
        for (int d = 0; d < 4; ++d) acc[a][d] = 0.f;

    #pragma unroll 2
    for (int m = 0; m < SLEN; ++m) {
        float4 xa = *(const float4*)(xpA + (size_t)m * FEAT);
        float4 va = *(const float4*)(vpA + m * EIG);
        float4 xb = *(const float4*)(xpB + (size_t)m * FEAT);
        float4 vb = *(const float4*)(vpB + m * EIG);
        acc[0][0] += xa.x*va.x; acc[0][1] += xa.x*va.y; acc[0][2] += xa.x*va.z; acc[0][3] += xa.x*va.w;
        acc[1][0] += xa.y*va.x; acc[1][1] += xa.y*va.y; acc[1][2] += xa.y*va.z; acc[1][3] += xa.y*va.w;
        acc[2][0] += xa.z*va.x; acc[2][1] += xa.z*va.y; acc[2][2] += xa.z*va.z; acc[2][3] += xa.z*va.w;
        acc[3][0] += xa.w*va.x; acc[3][1] += xa.w*va.y; acc[3][2] += xa.w*va.z; acc[3][3] += xa.w*va.w;
        acc[0][0] += xb.x*vb.x; acc[0][1] += xb.x*vb.y; acc[0][2] += xb.x*vb.z; acc[0][3] += xb.x*vb.w;
        acc[1][0] += xb.y*vb.x; acc[1][1] += xb.y*vb.y; acc[1][2] += xb.y*vb.z; acc[1][3] += xb.y*vb.w;
        acc[2][0] += xb.z*vb.x; acc[2][1] += xb.z*vb.y; acc[2][2] += xb.z*vb.z; acc[2][3] += xb.z*vb.w;
        acc[3][0] += xb.w*vb.x; acc[3][1] += xb.w*vb.y; acc[3][2] += xb.w*vb.z; acc[3][3] += xb.w*vb.w;
    }

    float* dst = g_zpart + (size_t)(ceff * BATCH + b) * (FEAT * EIG) + (4 * i4) * EIG + 4 * fq;
    #pragma unroll
    for (int a = 0; a < 4; ++a)
        *(float4*)(dst + a * EIG) = make_float4(acc[a][0], acc[a][1], acc[a][2], acc[a][3]);
}

// ---------------------------------------------------------------------------
// Reduce chunk partials: z = sum_c zpart[c]  (mostly L2-resident, ~26 MB)
// ---------------------------------------------------------------------------
__global__ void __launch_bounds__(128) k_reduce() {
    const int idx = blockIdx.x * 128 + threadIdx.x;  // 32768 threads total
    float s = 0.f;
    #pragma unroll 8
    for (int c = 0; c < CHUNKS_EFF; ++c)
        s += g_zpart[c * (BATCH * FEAT * EIG) + idx];
    g_z[idx] = s;
}

// ---------------------------------------------------------------------------
// Phase 2 REWRITE: w[b,j,e] = sum_n G[j,n,e-interleaved] * z[b,n], n=(i,f).
// grid (OUTD, 2), 512 threads = 16 warps (warp = e); block handles 16 batches.
// Lane l covers n = 4l + 128k (k=0..7): z LDG.128 fully COALESCED (4 wf/LDG
// instead of 32 in R5 -> 8x fewer L1 wavefronts). G cached in registers,
// gathered once per block (strided but one-time).
// ---------------------------------------------------------------------------
__global__ void __launch_bounds__(512) k_filter(const float* __restrict__ G) {
    const int j  = blockIdx.x;
    const int bh = blockIdx.y;            // batch half: 0/1
    const int e  = threadIdx.x >> 5;      // warp = e (0..15)
    const int l  = threadIdx.x & 31;

    // For n = 4l + 128k: i = (l>>2) + 8k, f = (l&3)*4.
    // G[j,i,e,f] addr = j*16384 + i*256 + e*16 + f ; k-stride = 8*256 = 2048.
    const float* Gp = G + (size_t)j * (FEAT * EIG * EIG)
                        + ((l >> 2)) * (EIG * EIG) + e * EIG + (l & 3) * 4;
    float4 g[8];
    #pragma unroll
    for (int k = 0; k < 8; ++k)
        g[k] = *(const float4*)(Gp + k * 8 * (EIG * EIG));

    const int b0 = bh * 16;
    #pragma unroll 2
    for (int bb = 0; bb < 16; ++bb) {
        const int b = b0 + bb;
        const float* zb = g_z + b * (FEAT * EIG) + 4 * l;
        float acc = 0.f;
        #pragma unroll
        for (int k = 0; k < 8; ++k) {
            float4 z4 = *(const float4*)(zb + k * 128);
            acc += g[k].x * z4.x + g[k].y * z4.y + g[k].z * z4.z + g[k].w * z4.w;
        }
        #pragma unroll
        for (int off = 16; off > 0; off >>= 1)
            acc += __shfl_down_sync(0xffffffffu, acc, off);
        if (l == 0) g_w[(b * OUTD + j) * EIG + e] = acc;
    }
}

// ---------------------------------------------------------------------------
// Phase 3 (proven 51us config): out[b,n,j] = sum_e V[n,e] * w[b,j,e]
// grid (ceil(NODES/64), BATCH), 256 threads, 4n x 4j tile, occ ~93%.
// ---------------------------------------------------------------------------
#define NTILE 64
__global__ void __launch_bounds__(256) k_output(const float* __restrict__ V,
                                                float* __restrict__ out) {
    const int tile = blockIdx.x, b = blockIdx.y;
    const int t = threadIdx.x;   // 256
    __shared__ __align__(16) float wt[EIG][68];
    __shared__ __align__(16) float vt[EIG][68];

    const int n0 = tile * NTILE;

    for (int k = t; k < OUTD * EIG; k += 256)
        wt[k & 15][k >> 4] = g_w[b * (OUTD * EIG) + k];
    for (int k = t; k < NTILE * EIG; k += 256) {
        int nl = k >> 4, e = k & 15;
        int n = n0 + nl;
        vt[e][nl] = (n < NODES) ? V[n * EIG + e] : 0.f;
    }
    __syncthreads();

    const int j0  = (t & 15) * 4;
    const int nl0 = (t >> 4) * 4;
    float acc[4][4];
    #pragma unroll
    for (int a = 0; a < 4; ++a)
        #pragma unroll
        for (int c = 0; c < 4; ++c) acc[a][c] = 0.f;

    #pragma unroll
    for (int e = 0; e < EIG; ++e) {
        float4 v4 = *(const float4*)&vt[e][nl0];
        float4 w4 = *(const float4*)&wt[e][j0];
        acc[0][0] += v4.x*w4.x; acc[0][1] += v4.x*w4.y; acc[0][2] += v4.x*w4.z; acc[0][3] += v4.x*w4.w;
        acc[1][0] += v4.y*w4.x; acc[1][1] += v4.y*w4.y; acc[1][2] += v4.y*w4.z; acc[1][3] += v4.y*w4.w;
        acc[2][0] += v4.z*w4.x; acc[2][1] += v4.z*w4.y; acc[2][2] += v4.z*w4.z; acc[2][3] += v4.z*w4.w;
        acc[3][0] += v4.w*w4.x; acc[3][1] += v4.w*w4.y; acc[3][2] += v4.w*w4.z; acc[3][3] += v4.w*w4.w;
    }

    float* ob = out + ((size_t)b * NODES + n0 + nl0) * OUTD + j0;
    #pragma unroll
    for (int ni = 0; ni < 4; ++ni) {
        if (n0 + nl0 + ni < NODES)
            *(float4*)(ob + (size_t)ni * OUTD) =
                make_float4(acc[ni][0], acc[ni][1], acc[ni][2], acc[ni][3]);
    }
}

extern "C" void kernel_launch(void* const* d_in, const int* in_sizes, int n_in,
                              void* d_out, int out_size) {
    const float* x = (const float*)d_in[0];   // (32, 20000, 64)
    const float* V = (const float*)d_in[1];   // (20000, 16)
    const float* G = (const float*)d_in[2];   // (64, 64, 16, 16)
    float* out = (float*)d_out;               // (32, 20000, 64)

    // ncu capture alignment: k_project is the 4th launch here
    k_nop<<<1, 32>>>();
    k_nop<<<1, 32>>>();
    k_nop<<<1, 32>>>();

    k_project<<<dim3(BATCH, CBLK), 128>>>(x, V);
    k_reduce<<<256, 128>>>();
    k_filter<<<dim3(OUTD, 2), 512>>>(G);
    k_output<<<dim3((NODES + NTILE - 1) / NTILE, BATCH), 256>>>(V, out);
}

// round 7
// speedup vs baseline: 1.8619x; 1.4704x over previous
#include <cuda_runtime.h>
#include <cstdint>

#define NODES 20000
#define BATCH 32
#define FEAT  64
#define OUTD  64
#define EIG   16

// --- phase-1 pipeline geometry ---
#define CBLK    50            // node-chunks (grid.y)
#define MPB     400           // m per block  (CBLK*MPB == NODES)
#define MT      40            // m per pipeline stage
#define NSTG    3             // stages in flight
#define NSTAGES (MPB / MT)    // 10

// Scratch (device globals — no allocation allowed)
__device__ float g_zpart[CBLK * BATCH * FEAT * EIG];  // 6.55 MB partials
__device__ float g_z[BATCH * FEAT * EIG];             // 128 KB
__device__ float g_w[BATCH * OUTD * EIG];             // 128 KB

__device__ __forceinline__ uint32_t s2u(const void* p) {
    return (uint32_t)__cvta_generic_to_shared(p);
}

// ---------------------------------------------------------------------------
// ncu-alignment no-ops: keep k_project as the captured launch.
// ---------------------------------------------------------------------------
__global__ void k_nop() {
    if (threadIdx.x == 0xFFFFFFFFu) g_z[0] = 0.f;  // never taken
}

// ---------------------------------------------------------------------------
// Phase 1 REWRITE: z[b,i,f] = sum_m V[m,f] * x[b,m,i]
// cp.async (LDGSTS) smem pipeline: loads decoupled from registers so
// outstanding DRAM bytes/SM is pipeline-depth-bound (~128 KB), not
// regfile-bound (~5 KB). grid (BATCH, CBLK), 256 thr.
// Thread (i4, fq, mg): 4i x 4f register tile over mg's 10-m strip;
// cross-mg reduction in smem at the end.
// ---------------------------------------------------------------------------
__global__ void __launch_bounds__(256) k_project(const float* __restrict__ x,
                                                 const float* __restrict__ V) {
    __shared__ __align__(16) float sx[NSTG][MT][FEAT];  // 30 KB
    __shared__ __align__(16) float sv[NSTG][MT][EIG];   // 7.5 KB

    const int b = blockIdx.x, c = blockIdx.y;
    const int t  = threadIdx.x;
    const int i4 = t & 15;          // i = 4*i4 .. +3
    const int fq = (t >> 4) & 3;    // f = 4*fq .. +3
    const int mg = t >> 6;          // m-group 0..3 within stage

    const int m0 = c * MPB;
    const float* xbase = x + ((size_t)b * NODES + m0) * FEAT;
    const float* vbase = V + (size_t)m0 * EIG;

    auto load_stage = [&](int s) {
        const int st = s % NSTG;
        const int mb = s * MT;
        // x tile: MT*FEAT/4 = 640 float4
        #pragma unroll
        for (int q = t; q < MT * FEAT / 4; q += 256) {
            const int m = q >> 4, iq = q & 15;
            const float* src = xbase + (size_t)(mb + m) * FEAT + iq * 4;
            uint32_t dst = s2u(&sx[st][m][iq * 4]);
            asm volatile("cp.async.cg.shared.global [%0], [%1], 16;\n"
                         :: "r"(dst), "l"(src));
        }
        // V tile: MT*EIG/4 = 160 float4
        if (t < MT * EIG / 4) {
            const int m = t >> 2, e4 = t & 3;
            const float* src = vbase + (mb + m) * EIG + e4 * 4;
            uint32_t dst = s2u(&sv[st][m][e4 * 4]);
            asm volatile("cp.async.cg.shared.global [%0], [%1], 16;\n"
                         :: "r"(dst), "l"(src));
        }
    };

    float acc[4][4];
    #pragma unroll
    for (int a = 0; a < 4; ++a)
        #pragma unroll
        for (int d = 0; d < 4; ++d) acc[a][d] = 0.f;

    // prologue: fill NSTG-1 stages
    #pragma unroll
    for (int s = 0; s < NSTG - 1; ++s) {
        load_stage(s);
        asm volatile("cp.async.commit_group;\n");
    }

    for (int s = 0; s < NSTAGES; ++s) {
        if (s + NSTG - 1 < NSTAGES) load_stage(s + NSTG - 1);
        asm volatile("cp.async.commit_group;\n");          // commit every iter (keeps count)
        asm volatile("cp.async.wait_group %0;\n" :: "n"(NSTG - 1));
        __syncthreads();                                    // stage s visible to all

        const int st = s % NSTG;
        #pragma unroll
        for (int mm = 0; mm < MT / 4; ++mm) {
            const int m = mg * (MT / 4) + mm;
            float4 x4 = *(const float4*)&sx[st][m][i4 * 4];
            float4 v4 = *(const float4*)&sv[st][m][fq * 4];
            acc[0][0] += x4.x*v4.x; acc[0][1] += x4.x*v4.y; acc[0][2] += x4.x*v4.z; acc[0][3] += x4.x*v4.w;
            acc[1][0] += x4.y*v4.x; acc[1][1] += x4.y*v4.y; acc[1][2] += x4.y*v4.z; acc[1][3] += x4.y*v4.w;
            acc[2][0] += x4.z*v4.x; acc[2][1] += x4.z*v4.y; acc[2][2] += x4.z*v4.z; acc[2][3] += x4.z*v4.w;
            acc[3][0] += x4.w*v4.x; acc[3][1] += x4.w*v4.y; acc[3][2] += x4.w*v4.z; acc[3][3] += x4.w*v4.w;
        }
        __syncthreads();                                    // slot safe to reuse
    }

    // cross-mg reduction (overlay scratch on sx; all stages consumed)
    float* sred = &sx[0][0][0];   // needs 4*1024 floats = 16 KB < 30 KB
    #pragma unroll
    for (int a = 0; a < 4; ++a)
        *(float4*)&sred[mg * 1024 + (4 * i4 + a) * EIG + 4 * fq] =
            make_float4(acc[a][0], acc[a][1], acc[a][2], acc[a][3]);
    __syncthreads();

    const int o = t * 4;   // 256 threads x 4 floats = 1024 outputs
    float4 r = make_float4(0.f, 0.f, 0.f, 0.f);
    #pragma unroll
    for (int g2 = 0; g2 < 4; ++g2) {
        float4 p = *(const float4*)&sred[g2 * 1024 + o];
        r.x += p.x; r.y += p.y; r.z += p.z; r.w += p.w;
    }
    *(float4*)&g_zpart[((size_t)c * BATCH + b) * 1024 + o] = r;
}

// ---------------------------------------------------------------------------
// Reduce chunk partials: z = sum_c zpart[c]   (6.55 MB, L2-resident)
// ---------------------------------------------------------------------------
__global__ void __launch_bounds__(128) k_reduce() {
    const int idx = blockIdx.x * 128 + threadIdx.x;  // 32768 threads total
    float s = 0.f;
    #pragma unroll 10
    for (int c = 0; c < CBLK; ++c)
        s += g_zpart[c * (BATCH * FEAT * EIG) + idx];
    g_z[idx] = s;
}

// ---------------------------------------------------------------------------
// Phase 2 (R6-proven coalesced version): w[b,j,e] = sum_n G-interleaved * z.
// grid (OUTD, 2), 512 threads = 16 warps (warp = e); coalesced z loads,
// G register-cached (one-time strided gather).
// ---------------------------------------------------------------------------
__global__ void __launch_bounds__(512) k_filter(const float* __restrict__ G) {
    const int j  = blockIdx.x;
    const int bh = blockIdx.y;            // batch half: 0/1
    const int e  = threadIdx.x >> 5;      // warp = e (0..15)
    const int l  = threadIdx.x & 31;

    // n = 4l + 128k: i = (l>>2) + 8k, f = (l&3)*4
    const float* Gp = G + (size_t)j * (FEAT * EIG * EIG)
                        + (l >> 2) * (EIG * EIG) + e * EIG + (l & 3) * 4;
    float4 g[8];
    #pragma unroll
    for (int k = 0; k < 8; ++k)
        g[k] = *(const float4*)(Gp + k * 8 * (EIG * EIG));

    const int b0 = bh * 16;
    #pragma unroll 2
    for (int bb = 0; bb < 16; ++bb) {
        const int b = b0 + bb;
        const float* zb = g_z + b * (FEAT * EIG) + 4 * l;
        float acc = 0.f;
        #pragma unroll
        for (int k = 0; k < 8; ++k) {
            float4 z4 = *(const float4*)(zb + k * 128);
            acc += g[k].x * z4.x + g[k].y * z4.y + g[k].z * z4.z + g[k].w * z4.w;
        }
        #pragma unroll
        for (int off = 16; off > 0; off >>= 1)
            acc += __shfl_down_sync(0xffffffffu, acc, off);
        if (l == 0) g_w[(b * OUTD + j) * EIG + e] = acc;
    }
}

// ---------------------------------------------------------------------------
// Phase 3 (proven 51us config): out[b,n,j] = sum_e V[n,e] * w[b,j,e]
// grid (ceil(NODES/64), BATCH), 256 threads, 4n x 4j tile, occ ~93%.
// ---------------------------------------------------------------------------
#define NTILE 64
__global__ void __launch_bounds__(256) k_output(const float* __restrict__ V,
                                                float* __restrict__ out) {
    const int tile = blockIdx.x, b = blockIdx.y;
    const int t = threadIdx.x;   // 256
    __shared__ __align__(16) float wt[EIG][68];
    __shared__ __align__(16) float vt[EIG][68];

    const int n0 = tile * NTILE;

    for (int k = t; k < OUTD * EIG; k += 256)
        wt[k & 15][k >> 4] = g_w[b * (OUTD * EIG) + k];
    for (int k = t; k < NTILE * EIG; k += 256) {
        int nl = k >> 4, e = k & 15;
        int n = n0 + nl;
        vt[e][nl] = (n < NODES) ? V[n * EIG + e] : 0.f;
    }
    __syncthreads();

    const int j0  = (t & 15) * 4;
    const int nl0 = (t >> 4) * 4;
    float acc[4][4];
    #pragma unroll
    for (int a = 0; a < 4; ++a)
        #pragma unroll
        for (int c = 0; c < 4; ++c) acc[a][c] = 0.f;

    #pragma unroll
    for (int e = 0; e < EIG; ++e) {
        float4 v4 = *(const float4*)&vt[e][nl0];
        float4 w4 = *(const float4*)&wt[e][j0];
        acc[0][0] += v4.x*w4.x; acc[0][1] += v4.x*w4.y; acc[0][2] += v4.x*w4.z; acc[0][3] += v4.x*w4.w;
        acc[1][0] += v4.y*w4.x; acc[1][1] += v4.y*w4.y; acc[1][2] += v4.y*w4.z; acc[1][3] += v4.y*w4.w;
        acc[2][0] += v4.z*w4.x; acc[2][1] += v4.z*w4.y; acc[2][2] += v4.z*w4.z; acc[2][3] += v4.z*w4.w;
        acc[3][0] += v4.w*w4.x; acc[3][1] += v4.w*w4.y; acc[3][2] += v4.w*w4.z; acc[3][3] += v4.w*w4.w;
    }

    float* ob = out + ((size_t)b * NODES + n0 + nl0) * OUTD + j0;
    #pragma unroll
    for (int ni = 0; ni < 4; ++ni) {
        if (n0 + nl0 + ni < NODES)
            *(float4*)(ob + (size_t)ni * OUTD) =
                make_float4(acc[ni][0], acc[ni][1], acc[ni][2], acc[ni][3]);
    }
}

extern "C" void kernel_launch(void* const* d_in, const int* in_sizes, int n_in,
                              void* d_out, int out_size) {
    const float* x = (const float*)d_in[0];   // (32, 20000, 64)
    const float* V = (const float*)d_in[1];   // (20000, 16)
    const float* G = (const float*)d_in[2];   // (64, 64, 16, 16)
    float* out = (float*)d_out;               // (32, 20000, 64)

    // ncu capture alignment: k_project is the 4th launch here
    k_nop<<<1, 32>>>();
    k_nop<<<1, 32>>>();
    k_nop<<<1, 32>>>();

    k_project<<<dim3(BATCH, CBLK), 256>>>(x, V);
    k_reduce<<<256, 128>>>();
    k_filter<<<dim3(OUTD, 2), 512>>>(G);
    k_output<<<dim3((NODES + NTILE - 1) / NTILE, BATCH), 256>>>(V, out);
}

// round 8
// speedup vs baseline: 1.9704x; 1.0583x over previous
#include <cuda_runtime.h>
#include <cstdint>

#define NODES 20000
#define BATCH 32
#define FEAT  64
#define OUTD  64
#define EIG   16

// --- phase-1 pipeline geometry ---
#define CBLK    50            // node-chunks (grid.y)
#define MPB     400           // m per block  (CBLK*MPB == NODES)
#define MT      40            // m per pipeline stage
#define NSTG    3             // stages in flight
#define NSTAGES (MPB / MT)    // 10

// Scratch (device globals — no allocation allowed)
__device__ float g_zpart[CBLK * BATCH * FEAT * EIG];  // 6.55 MB partials
__device__ float g_z[BATCH * FEAT * EIG];             // 128 KB
__device__ float g_w[BATCH * OUTD * EIG];             // 128 KB

__device__ __forceinline__ uint32_t s2u(const void* p) {
    return (uint32_t)__cvta_generic_to_shared(p);
}
// ---- packed f32x2 helpers (PTX-only; doubles fp32 FMA throughput) ----
__device__ __forceinline__ unsigned long long pack2(float a, float b) {
    unsigned long long r;
    asm("mov.b64 %0, {%1, %2};" : "=l"(r) : "f"(a), "f"(b));
    return r;
}
__device__ __forceinline__ void unpack2(unsigned long long v, float& a, float& b) {
    asm("mov.b64 {%0, %1}, %2;" : "=f"(a), "=f"(b) : "l"(v));
}
__device__ __forceinline__ unsigned long long fma2(unsigned long long a,
                                                   unsigned long long b,
                                                   unsigned long long c) {
    unsigned long long d;
    asm("fma.rn.f32x2 %0, %1, %2, %3;" : "=l"(d) : "l"(a), "l"(b), "l"(c));
    return d;
}

// ---------------------------------------------------------------------------
// Phase 1: z[b,i,f] = sum_m V[m,f] * x[b,m,i]
// cp.async pipeline (R7-proven) + FFMA2 mainloop.
// 256 thr: i4 = t&15 (4 i's), fh = (t>>4)&1 (8 f's), mg = t>>5 (8 m-groups,
// 5 m each per 40-m stage). Per m: LDS x4 + 2x LDS v-pairs + 4 PACK +
// 16 FFMA2 (one warp per m). Cross-mg smem reduction at the end.
// ---------------------------------------------------------------------------
__global__ void __launch_bounds__(256) k_project(const float* __restrict__ x,
                                                 const float* __restrict__ V) {
    __shared__ __align__(16) float sbuf[NSTG * MT * FEAT + NSTG * MT * EIG]; // 38.4 KB
    float* sx = sbuf;                          // [NSTG][MT][FEAT]
    float* sv = sbuf + NSTG * MT * FEAT;       // [NSTG][MT][EIG]

    const int b = blockIdx.x, c = blockIdx.y;
    const int t  = threadIdx.x;
    const int i4 = t & 15;          // i = 4*i4 .. +3
    const int fh = (t >> 4) & 1;    // f-half: f = fh*8 .. +7
    const int mg = t >> 5;          // m-group 0..7 (5 m per stage)

    const int m0 = c * MPB;
    const float* xbase = x + ((size_t)b * NODES + m0) * FEAT;
    const float* vbase = V + (size_t)m0 * EIG;

    auto load_stage = [&](int s) {
        const int st = s % NSTG;
        const int mb = s * MT;
        #pragma unroll
        for (int q = t; q < MT * FEAT / 4; q += 256) {       // 640 float4
            const int m = q >> 4, iq = q & 15;
            const float* src = xbase + (size_t)(mb + m) * FEAT + iq * 4;
            uint32_t dst = s2u(&sx[(st * MT + m) * FEAT + iq * 4]);
            asm volatile("cp.async.cg.shared.global [%0], [%1], 16;\n"
                         :: "r"(dst), "l"(src));
        }
        if (t < MT * EIG / 4) {                              // 160 float4
            const int m = t >> 2, e4 = t & 3;
            const float* src = vbase + (mb + m) * EIG + e4 * 4;
            uint32_t dst = s2u(&sv[(st * MT + m) * EIG + e4 * 4]);
            asm volatile("cp.async.cg.shared.global [%0], [%1], 16;\n"
                         :: "r"(dst), "l"(src));
        }
    };

    unsigned long long acc2[4][4];  // [i][f-pair]
    #pragma unroll
    for (int a = 0; a < 4; ++a)
        #pragma unroll
        for (int p = 0; p < 4; ++p) acc2[a][p] = pack2(0.f, 0.f);

    #pragma unroll
    for (int s = 0; s < NSTG - 1; ++s) {
        load_stage(s);
        asm volatile("cp.async.commit_group;\n");
    }

    for (int s = 0; s < NSTAGES; ++s) {
        if (s + NSTG - 1 < NSTAGES) load_stage(s + NSTG - 1);
        asm volatile("cp.async.commit_group;\n");
        asm volatile("cp.async.wait_group %0;\n" :: "n"(NSTG - 1));
        __syncthreads();

        const int st = s % NSTG;
        #pragma unroll
        for (int mm = 0; mm < MT / 8; ++mm) {
            const int m = mg * (MT / 8) + mm;
            float4 x4 = *(const float4*)&sx[(st * MT + m) * FEAT + i4 * 4];
            ulonglong2 va = *(const ulonglong2*)&sv[(st * MT + m) * EIG + fh * 8];
            unsigned long long xd0 = pack2(x4.x, x4.x);
            unsigned long long xd1 = pack2(x4.y, x4.y);
            unsigned long long xd2 = pack2(x4.z, x4.z);
            unsigned long long xd3 = pack2(x4.w, x4.w);
            acc2[0][0] = fma2(xd0, va.x, acc2[0][0]);
            acc2[0][1] = fma2(xd0, va.y, acc2[0][1]);
            acc2[1][0] = fma2(xd1, va.x, acc2[1][0]);
            acc2[1][1] = fma2(xd1, va.y, acc2[1][1]);
            acc2[2][0] = fma2(xd2, va.x, acc2[2][0]);
            acc2[2][1] = fma2(xd2, va.y, acc2[2][1]);
            acc2[3][0] = fma2(xd3, va.x, acc2[3][0]);
            acc2[3][1] = fma2(xd3, va.y, acc2[3][1]);
            ulonglong2 vb = *(const ulonglong2*)&sv[(st * MT + m) * EIG + fh * 8 + 4];
            acc2[0][2] = fma2(xd0, vb.x, acc2[0][2]);
            acc2[0][3] = fma2(xd0, vb.y, acc2[0][3]);
            acc2[1][2] = fma2(xd1, vb.x, acc2[1][2]);
            acc2[1][3] = fma2(xd1, vb.y, acc2[1][3]);
            acc2[2][2] = fma2(xd2, vb.x, acc2[2][2]);
            acc2[2][3] = fma2(xd2, vb.y, acc2[2][3]);
            acc2[3][2] = fma2(xd3, vb.x, acc2[3][2]);
            acc2[3][3] = fma2(xd3, vb.y, acc2[3][3]);
        }
        __syncthreads();
    }

    // cross-mg reduction: overlay 8 x 1024 floats on sbuf (9600 floats avail)
    asm volatile("cp.async.wait_group 0;\n");
    __syncthreads();
    #pragma unroll
    for (int a = 0; a < 4; ++a)
        #pragma unroll
        for (int p = 0; p < 4; ++p) {
            float lo, hi;
            unpack2(acc2[a][p], lo, hi);
            *(float2*)&sbuf[mg * 1024 + (4 * i4 + a) * EIG + fh * 8 + 2 * p] =
                make_float2(lo, hi);
        }
    __syncthreads();

    const int o = t * 4;   // 256 threads x 4 floats = 1024 outputs
    float4 r = make_float4(0.f, 0.f, 0.f, 0.f);
    #pragma unroll
    for (int g2 = 0; g2 < 8; ++g2) {
        float4 p = *(const float4*)&sbuf[g2 * 1024 + o];
        r.x += p.x; r.y += p.y; r.z += p.z; r.w += p.w;
    }
    *(float4*)&g_zpart[((size_t)c * BATCH + b) * 1024 + o] = r;
}

// ---------------------------------------------------------------------------
// Reduce chunk partials: z = sum_c zpart[c]   (6.55 MB, L2-resident)
// ---------------------------------------------------------------------------
__global__ void __launch_bounds__(128) k_reduce() {
    const int idx = blockIdx.x * 128 + threadIdx.x;  // 32768 threads total
    float s = 0.f;
    #pragma unroll 10
    for (int c = 0; c < CBLK; ++c)
        s += g_zpart[c * (BATCH * FEAT * EIG) + idx];
    g_z[idx] = s;
}

// ---------------------------------------------------------------------------
// Phase 2 (R6-proven): w[b,j,e] = sum_n G-interleaved * z. Coalesced z loads,
// G register-cached. grid (OUTD, 2), 512 threads = 16 warps (warp = e).
// ---------------------------------------------------------------------------
__global__ void __launch_bounds__(512) k_filter(const float* __restrict__ G) {
    const int j  = blockIdx.x;
    const int bh = blockIdx.y;
    const int e  = threadIdx.x >> 5;
    const int l  = threadIdx.x & 31;

    const float* Gp = G + (size_t)j * (FEAT * EIG * EIG)
                        + (l >> 2) * (EIG * EIG) + e * EIG + (l & 3) * 4;
    float4 g[8];
    #pragma unroll
    for (int k = 0; k < 8; ++k)
        g[k] = *(const float4*)(Gp + k * 8 * (EIG * EIG));

    const int b0 = bh * 16;
    #pragma unroll 2
    for (int bb = 0; bb < 16; ++bb) {
        const int b = b0 + bb;
        const float* zb = g_z + b * (FEAT * EIG) + 4 * l;
        float acc = 0.f;
        #pragma unroll
        for (int k = 0; k < 8; ++k) {
            float4 z4 = *(const float4*)(zb + k * 128);
            acc += g[k].x * z4.x + g[k].y * z4.y + g[k].z * z4.z + g[k].w * z4.w;
        }
        #pragma unroll
        for (int off = 16; off > 0; off >>= 1)
            acc += __shfl_down_sync(0xffffffffu, acc, off);
        if (l == 0) g_w[(b * OUTD + j) * EIG + e] = acc;
    }
}

// ---------------------------------------------------------------------------
// Phase 3 REWRITE: out[b,n,j] = sum_e V[n,e] * w[b,j,e]
// grid (50, BATCH), 256 thr = 8 warps; block = 400 nodes of one batch.
// Lane: j-quad (lane&15), n-stream (lane>>4). w for the j-quad cached in
// registers as 16e x 2 packed j-pairs (loaded ONCE per block from transposed
// smem -> zero per-iteration w traffic). Inner: v broadcast LDS + PACK +
// FFMA2. Stores: warp covers 512B contiguous per 2n step.
// ---------------------------------------------------------------------------
#define NTILE2 400
__global__ void __launch_bounds__(256) k_output(const float* __restrict__ V,
                                                float* __restrict__ out) {
    const int tile = blockIdx.x, b = blockIdx.y;
    const int t = threadIdx.x;
    const int lane = t & 31, wid = t >> 5;
    const int j4 = lane & 15;          // j0 = 4*j4
    const int npar = lane >> 4;        // n-stream 0/1

    __shared__ __align__(16) float swt[EIG][68];            // w transposed [e][j]
    __shared__ __align__(16) float vt[NTILE2 * EIG];        // 25.6 KB [n][e]

    const int n0 = tile * NTILE2;

    // g_w[b][j][e] -> swt[e][j]  (coalesced read, scattered smem write)
    for (int k = t; k < OUTD * EIG; k += 256)
        swt[k & 15][k >> 4] = g_w[b * (OUTD * EIG) + k];
    // V rows n0..n0+399 -> vt[n][e]  (NODES = 50*400 exactly; no bounds)
    for (int k = t; k < NTILE2 * EIG / 4; k += 256)
        *(float4*)&vt[k * 4] = *(const float4*)&V[(size_t)n0 * EIG + k * 4];
    __syncthreads();

    // one-time: cache w j-pairs in registers: wp[e][0]=(j0,j0+1), [1]=(j0+2,j0+3)
    unsigned long long wp[EIG][2];
    #pragma unroll
    for (int e = 0; e < EIG; ++e) {
        float4 wv = *(const float4*)&swt[e][j4 * 4];
        wp[e][0] = pack2(wv.x, wv.y);
        wp[e][1] = pack2(wv.z, wv.w);
    }

    // warp handles 50 n (25 steps of 2); lane's n = base + 2*step + npar
    const int nw0 = wid * 50;
    float* ob = out + ((size_t)b * NODES + n0 + nw0 + npar) * OUTD + j4 * 4;

    for (int s = 0; s < 25; ++s) {
        const float* vp = &vt[(nw0 + 2 * s + npar) * EIG];
        float4 va = *(const float4*)(vp);
        float4 vb = *(const float4*)(vp + 4);
        float4 vc = *(const float4*)(vp + 8);
        float4 vd = *(const float4*)(vp + 12);

        unsigned long long a0 = pack2(0.f, 0.f), a1 = pack2(0.f, 0.f);
        #define STEP_E(e, vv)                                        \
            { unsigned long long vdup = pack2(vv, vv);               \
              a0 = fma2(vdup, wp[e][0], a0);                         \
              a1 = fma2(vdup, wp[e][1], a1); }
        STEP_E(0,  va.x) STEP_E(1,  va.y) STEP_E(2,  va.z) STEP_E(3,  va.w)
        STEP_E(4,  vb.x) STEP_E(5,  vb.y) STEP_E(6,  vb.z) STEP_E(7,  vb.w)
        STEP_E(8,  vc.x) STEP_E(9,  vc.y) STEP_E(10, vc.z) STEP_E(11, vc.w)
        STEP_E(12, vd.x) STEP_E(13, vd.y) STEP_E(14, vd.z) STEP_E(15, vd.w)
        #undef STEP_E

        float o0, o1, o2, o3;
        unpack2(a0, o0, o1);
        unpack2(a1, o2, o3);
        *(float4*)(ob + (size_t)(2 * s) * OUTD) = make_float4(o0, o1, o2, o3);
    }
}

extern "C" void kernel_launch(void* const* d_in, const int* in_sizes, int n_in,
                              void* d_out, int out_size) {
    const float* x = (const float*)d_in[0];   // (32, 20000, 64)
    const float* V = (const float*)d_in[1];   // (20000, 16)
    const float* G = (const float*)d_in[2];   // (64, 64, 16, 16)
    float* out = (float*)d_out;               // (32, 20000, 64)

    // no nops: ncu capture (6th process launch) lands on k_output
    k_project<<<dim3(BATCH, CBLK), 256>>>(x, V);
    k_reduce<<<256, 128>>>();
    k_filter<<<dim3(OUTD, 2), 512>>>(G);
    k_output<<<dim3(CBLK, BATCH), 256>>>(V, out);
}

// round 9
// speedup vs baseline: 2.0641x; 1.0475x over previous
#include <cuda_runtime.h>
#include <cstdint>

#define NODES 20000
#define BATCH 32
#define FEAT  64
#define OUTD  64
#define EIG   16

// --- phase-1 pipeline geometry ---
#define CBLK    50            // node-chunks (grid.y)
#define MPB     400           // m per block  (CBLK*MPB == NODES)
#define MT      40            // m per pipeline stage
#define NSTG    3             // stages in flight
#define NSTAGES (MPB / MT)    // 10

// Scratch (device globals — no allocation allowed)
__device__ float g_zpart[CBLK * BATCH * FEAT * EIG];  // 6.55 MB partials
__device__ float g_z[BATCH * FEAT * EIG];             // 128 KB
__device__ float g_w[BATCH * OUTD * EIG];             // 128 KB

__device__ __forceinline__ uint32_t s2u(const void* p) {
    return (uint32_t)__cvta_generic_to_shared(p);
}
// ---- packed f32x2 helpers (PTX-only; doubles fp32 FMA throughput) ----
__device__ __forceinline__ unsigned long long pack2(float a, float b) {
    unsigned long long r;
    asm("mov.b64 %0, {%1, %2};" : "=l"(r) : "f"(a), "f"(b));
    return r;
}
__device__ __forceinline__ void unpack2(unsigned long long v, float& a, float& b) {
    asm("mov.b64 {%0, %1}, %2;" : "=f"(a), "=f"(b) : "l"(v));
}
__device__ __forceinline__ unsigned long long fma2(unsigned long long a,
                                                   unsigned long long b,
                                                   unsigned long long c) {
    unsigned long long d;
    asm("fma.rn.f32x2 %0, %1, %2, %3;" : "=l"(d) : "l"(a), "l"(b), "l"(c));
    return d;
}

// ---------------------------------------------------------------------------
// Phase 1 (R8-proven): z[b,i,f] = sum_m V[m,f] * x[b,m,i]
// cp.async pipeline + FFMA2 mainloop. grid (BATCH, CBLK), 256 thr.
// ---------------------------------------------------------------------------
__global__ void __launch_bounds__(256) k_project(const float* __restrict__ x,
                                                 const float* __restrict__ V) {
    __shared__ __align__(16) float sbuf[NSTG * MT * FEAT + NSTG * MT * EIG]; // 38.4 KB
    float* sx = sbuf;                          // [NSTG][MT][FEAT]
    float* sv = sbuf + NSTG * MT * FEAT;       // [NSTG][MT][EIG]

    const int b = blockIdx.x, c = blockIdx.y;
    const int t  = threadIdx.x;
    const int i4 = t & 15;          // i = 4*i4 .. +3
    const int fh = (t >> 4) & 1;    // f-half: f = fh*8 .. +7
    const int mg = t >> 5;          // m-group 0..7 (5 m per stage)

    const int m0 = c * MPB;
    const float* xbase = x + ((size_t)b * NODES + m0) * FEAT;
    const float* vbase = V + (size_t)m0 * EIG;

    auto load_stage = [&](int s) {
        const int st = s % NSTG;
        const int mb = s * MT;
        #pragma unroll
        for (int q = t; q < MT * FEAT / 4; q += 256) {       // 640 float4
            const int m = q >> 4, iq = q & 15;
            const float* src = xbase + (size_t)(mb + m) * FEAT + iq * 4;
            uint32_t dst = s2u(&sx[(st * MT + m) * FEAT + iq * 4]);
            asm volatile("cp.async.cg.shared.global [%0], [%1], 16;\n"
                         :: "r"(dst), "l"(src));
        }
        if (t < MT * EIG / 4) {                              // 160 float4
            const int m = t >> 2, e4 = t & 3;
            const float* src = vbase + (mb + m) * EIG + e4 * 4;
            uint32_t dst = s2u(&sv[(st * MT + m) * EIG + e4 * 4]);
            asm volatile("cp.async.cg.shared.global [%0], [%1], 16;\n"
                         :: "r"(dst), "l"(src));
        }
    };

    unsigned long long acc2[4][4];  // [i][f-pair]
    #pragma unroll
    for (int a = 0; a < 4; ++a)
        #pragma unroll
        for (int p = 0; p < 4; ++p) acc2[a][p] = pack2(0.f, 0.f);

    #pragma unroll
    for (int s = 0; s < NSTG - 1; ++s) {
        load_stage(s);
        asm volatile("cp.async.commit_group;\n");
    }

    for (int s = 0; s < NSTAGES; ++s) {
        if (s + NSTG - 1 < NSTAGES) load_stage(s + NSTG - 1);
        asm volatile("cp.async.commit_group;\n");
        asm volatile("cp.async.wait_group %0;\n" :: "n"(NSTG - 1));
        __syncthreads();

        const int st = s % NSTG;
        #pragma unroll
        for (int mm = 0; mm < MT / 8; ++mm) {
            const int m = mg * (MT / 8) + mm;
            float4 x4 = *(const float4*)&sx[(st * MT + m) * FEAT + i4 * 4];
            ulonglong2 va = *(const ulonglong2*)&sv[(st * MT + m) * EIG + fh * 8];
            unsigned long long xd0 = pack2(x4.x, x4.x);
            unsigned long long xd1 = pack2(x4.y, x4.y);
            unsigned long long xd2 = pack2(x4.z, x4.z);
            unsigned long long xd3 = pack2(x4.w, x4.w);
            acc2[0][0] = fma2(xd0, va.x, acc2[0][0]);
            acc2[0][1] = fma2(xd0, va.y, acc2[0][1]);
            acc2[1][0] = fma2(xd1, va.x, acc2[1][0]);
            acc2[1][1] = fma2(xd1, va.y, acc2[1][1]);
            acc2[2][0] = fma2(xd2, va.x, acc2[2][0]);
            acc2[2][1] = fma2(xd2, va.y, acc2[2][1]);
            acc2[3][0] = fma2(xd3, va.x, acc2[3][0]);
            acc2[3][1] = fma2(xd3, va.y, acc2[3][1]);
            ulonglong2 vb = *(const ulonglong2*)&sv[(st * MT + m) * EIG + fh * 8 + 4];
            acc2[0][2] = fma2(xd0, vb.x, acc2[0][2]);
            acc2[0][3] = fma2(xd0, vb.y, acc2[0][3]);
            acc2[1][2] = fma2(xd1, vb.x, acc2[1][2]);
            acc2[1][3] = fma2(xd1, vb.y, acc2[1][3]);
            acc2[2][2] = fma2(xd2, vb.x, acc2[2][2]);
            acc2[2][3] = fma2(xd2, vb.y, acc2[2][3]);
            acc2[3][2] = fma2(xd3, vb.x, acc2[3][2]);
            acc2[3][3] = fma2(xd3, vb.y, acc2[3][3]);
        }
        __syncthreads();
    }

    // cross-mg reduction: overlay 8 x 1024 floats on sbuf
    asm volatile("cp.async.wait_group 0;\n");
    __syncthreads();
    #pragma unroll
    for (int a = 0; a < 4; ++a)
        #pragma unroll
        for (int p = 0; p < 4; ++p) {
            float lo, hi;
            unpack2(acc2[a][p], lo, hi);
            *(float2*)&sbuf[mg * 1024 + (4 * i4 + a) * EIG + fh * 8 + 2 * p] =
                make_float2(lo, hi);
        }
    __syncthreads();

    const int o = t * 4;   // 256 threads x 4 floats = 1024 outputs
    float4 r = make_float4(0.f, 0.f, 0.f, 0.f);
    #pragma unroll
    for (int g2 = 0; g2 < 8; ++g2) {
        float4 p = *(const float4*)&sbuf[g2 * 1024 + o];
        r.x += p.x; r.y += p.y; r.z += p.z; r.w += p.w;
    }
    *(float4*)&g_zpart[((size_t)c * BATCH + b) * 1024 + o] = r;
}

// ---------------------------------------------------------------------------
// Reduce chunk partials: z = sum_c zpart[c]   (6.55 MB, L2-resident)
// ---------------------------------------------------------------------------
__global__ void __launch_bounds__(128) k_reduce() {
    const int idx = blockIdx.x * 128 + threadIdx.x;  // 32768 threads total
    float s = 0.f;
    #pragma unroll 10
    for (int c = 0; c < CBLK; ++c)
        s += g_zpart[c * (BATCH * FEAT * EIG) + idx];
    g_z[idx] = s;
}

// ---------------------------------------------------------------------------
// Phase 2 (R6-proven): w[b,j,e] = sum_n G-interleaved * z. Coalesced z loads,
// G register-cached. grid (OUTD, 2), 512 threads = 16 warps (warp = e).
// ---------------------------------------------------------------------------
__global__ void __launch_bounds__(512) k_filter(const float* __restrict__ G) {
    const int j  = blockIdx.x;
    const int bh = blockIdx.y;
    const int e  = threadIdx.x >> 5;
    const int l  = threadIdx.x & 31;

    const float* Gp = G + (size_t)j * (FEAT * EIG * EIG)
                        + (l >> 2) * (EIG * EIG) + e * EIG + (l & 3) * 4;
    float4 g[8];
    #pragma unroll
    for (int k = 0; k < 8; ++k)
        g[k] = *(const float4*)(Gp + k * 8 * (EIG * EIG));

    const int b0 = bh * 16;
    #pragma unroll 2
    for (int bb = 0; bb < 16; ++bb) {
        const int b = b0 + bb;
        const float* zb = g_z + b * (FEAT * EIG) + 4 * l;
        float acc = 0.f;
        #pragma unroll
        for (int k = 0; k < 8; ++k) {
            float4 z4 = *(const float4*)(zb + k * 128);
            acc += g[k].x * z4.x + g[k].y * z4.y + g[k].z * z4.z + g[k].w * z4.w;
        }
        #pragma unroll
        for (int off = 16; off > 0; off >>= 1)
            acc += __shfl_down_sync(0xffffffffu, acc, off);
        if (l == 0) g_w[(b * OUTD + j) * EIG + e] = acc;
    }
}

// ---------------------------------------------------------------------------
// Phase 3: out[b,n,j] = sum_e V[n,e] * w[b,j,e]
// OCCUPANCY FIX vs R8: lane owns a j-PAIR (not quad) -> w-cache is 16 ull
// = 32 regs (half of R8); __launch_bounds__(256,4) caps regs at 64 ->
// 4 blocks/SM, occ ~50% (was 23%). Warp covers all 64 j per node; two
// independent FFMA2 chains (even/odd e). Store: STG.64/lane, 256B/warp.
// grid (50, BATCH), 256 thr = 8 warps; warp handles 50 consecutive nodes.
// ---------------------------------------------------------------------------
#define NTILE2 400
__global__ void __launch_bounds__(256, 4) k_output(const float* __restrict__ V,
                                                   float* __restrict__ out) {
    const int tile = blockIdx.x, b = blockIdx.y;
    const int t = threadIdx.x;
    const int lane = t & 31, wid = t >> 5;

    __shared__ __align__(16) float swt[EIG][66];            // w transposed [e][j]
    __shared__ __align__(16) float vt[NTILE2 * EIG];        // 25.6 KB [n][e]

    const int n0 = tile * NTILE2;

    // g_w[b][j][e] -> swt[e][j]  (coalesced read, scattered smem write)
    for (int k = t; k < OUTD * EIG; k += 256)
        swt[k & 15][k >> 4] = g_w[b * (OUTD * EIG) + k];
    // V rows n0..n0+399 -> vt[n][e]  (NODES = 50*400 exactly; no bounds)
    for (int k = t; k < NTILE2 * EIG / 4; k += 256)
        *(float4*)&vt[k * 4] = *(const float4*)&V[(size_t)n0 * EIG + k * 4];
    __syncthreads();

    // one-time: lane's j-pair (2*lane, 2*lane+1) cached packed: 16 ull
    unsigned long long wp[EIG];
    #pragma unroll
    for (int e = 0; e < EIG; ++e) {
        float2 wv = *(const float2*)&swt[e][lane * 2];
        wp[e] = pack2(wv.x, wv.y);
    }

    const int nw0 = wid * 50;
    float* ob = out + ((size_t)b * NODES + n0 + nw0) * OUTD + lane * 2;

    for (int s = 0; s < 50; ++s) {
        const float* vp = &vt[(nw0 + s) * EIG];
        unsigned long long a0 = pack2(0.f, 0.f), a1 = pack2(0.f, 0.f);

        float4 va = *(const float4*)(vp);
        a0 = fma2(pack2(va.x, va.x), wp[0], a0);
        a1 = fma2(pack2(va.y, va.y), wp[1], a1);
        a0 = fma2(pack2(va.z, va.z), wp[2], a0);
        a1 = fma2(pack2(va.w, va.w), wp[3], a1);
        float4 vb = *(const float4*)(vp + 4);
        a0 = fma2(pack2(vb.x, vb.x), wp[4], a0);
        a1 = fma2(pack2(vb.y, vb.y), wp[5], a1);
        a0 = fma2(pack2(vb.z, vb.z), wp[6], a0);
        a1 = fma2(pack2(vb.w, vb.w), wp[7], a1);
        float4 vc = *(const float4*)(vp + 8);
        a0 = fma2(pack2(vc.x, vc.x), wp[8], a0);
        a1 = fma2(pack2(vc.y, vc.y), wp[9], a1);
        a0 = fma2(pack2(vc.z, vc.z), wp[10], a0);
        a1 = fma2(pack2(vc.w, vc.w), wp[11], a1);
        float4 vd = *(const float4*)(vp + 12);
        a0 = fma2(pack2(vd.x, vd.x), wp[12], a0);
        a1 = fma2(pack2(vd.y, vd.y), wp[13], a1);
        a0 = fma2(pack2(vd.z, vd.z), wp[14], a0);
        a1 = fma2(pack2(vd.w, vd.w), wp[15], a1);

        float x0, x1, y0, y1;
        unpack2(a0, x0, x1);
        unpack2(a1, y0, y1);
        *(float2*)(ob + (size_t)s * OUTD) = make_float2(x0 + y0, x1 + y1);
    }
}

extern "C" void kernel_launch(void* const* d_in, const int* in_sizes, int n_in,
                              void* d_out, int out_size) {
    const float* x = (const float*)d_in[0];   // (32, 20000, 64)
    const float* V = (const float*)d_in[1];   // (20000, 16)
    const float* G = (const float*)d_in[2];   // (64, 64, 16, 16)
    float* out = (float*)d_out;               // (32, 20000, 64)

    // no nops: ncu capture (6th process launch) lands on k_output
    k_project<<<dim3(BATCH, CBLK), 256>>>(x, V);
    k_reduce<<<256, 128>>>();
    k_filter<<<dim3(OUTD, 2), 512>>>(G);
    k_output<<<dim3(CBLK, BATCH), 256>>>(V, out);
}